// round 16
// baseline (speedup 1.0000x reference)
#include <cuda_runtime.h>
#include <cuda_fp16.h>
#include <cstdint>

#define N0   50000
#define NM   25000
#define DD   128
#define NE   800000
#define NE12 400000

// ---------------- per-list counters ----------------
#define B_E1D  0
#define B_E2D  (B_E1D + NM)
#define B_E3D  (B_E2D + NM)
#define B_E1S  (B_E3D + NM)
#define B_E2S  (B_E1S + N0)
#define B_E3S  (B_E2S + N0)
#define B_E12D (B_E3S + N0)
#define B_E12S (B_E12D + NM)
#define B_E13D (B_E12S + NM)
#define B_E13S (B_E13D + NM)
#define TOTC   (B_E13S + NM)

// ---------------- padded bucket storage ----------------
#define CAPM_SH 7
#define CAP0_SH 6
#define WB_E1D 0
#define WB_E2D (WB_E1D + (NM << CAPM_SH))
#define WB_E3D (WB_E2D + (NM << CAPM_SH))
#define WB_E1S (WB_E3D + (NM << CAPM_SH))
#define TOTW   (WB_E1S + (N0 << CAP0_SH))
#define UB_E2S  0
#define UB_E3S  (UB_E2S + (N0 << CAP0_SH))
#define UB_E12D (UB_E3S + (N0 << CAP0_SH))
#define UB_E12S (UB_E12D + (NM << CAP0_SH))
#define UB_E13D (UB_E12S + (NM << CAP0_SH))
#define UB_E13S (UB_E13D + (NM << CAP0_SH))
#define TOTU    (UB_E13S + (NM << CAP0_SH))

// ---------------- static device scratch ----------------
__device__ int    g_cnt[TOTC];
__device__ int2   g_giw[TOTW];
__device__ int    g_gi[TOTU];

__device__ __half g_xn16[(long long)N0 * DD];
__device__ __half g_net1[NM * DD];
__device__ __half g_midB[NM * DD];
__device__ __half g_midC[NM * DD];
__device__ __half g_midD[NM * DD];
__device__ __half g_n3bD[NM * DD];
__device__ __half g_midE[NM * DD];
__device__ __half g_n3bE[NM * DD];
__device__ __half g_sumA[(long long)N0 * DD];
__device__ __half g_sumB[(long long)N0 * DD];
__device__ __half g_sumC[(long long)N0 * DD];
__device__ __half g_sumD[(long long)N0 * DD];
__device__ __half g_sumE[(long long)N0 * DD];
__device__ float  g_allm[(long long)N0 * 5 * DD];

// ---------------- fp16 helpers ----------------
__device__ __forceinline__ void acc4w(float4& a, uint2 v, float w) {
    float2 p = __half22float2(*(__half2*)&v.x);
    float2 q = __half22float2(*(__half2*)&v.y);
    a.x += p.x * w; a.y += p.y * w; a.z += q.x * w; a.w += q.y * w;
}
__device__ __forceinline__ void acc4(float4& a, uint2 v) {
    float2 p = __half22float2(*(__half2*)&v.x);
    float2 q = __half22float2(*(__half2*)&v.y);
    a.x += p.x; a.y += p.y; a.z += q.x; a.w += q.y;
}
__device__ __forceinline__ uint2 pack4(float4 a) {
    __half2 h0 = __floats2half2_rn(a.x, a.y);
    __half2 h1 = __floats2half2_rn(a.z, a.w);
    uint2 r; r.x = *(unsigned*)&h0; r.y = *(unsigned*)&h1; return r;
}

// ---------------- one-pass bucketed build (2 edges/thread) ----------------
__global__ void k_fillA(const int* __restrict__ e1s, const int* __restrict__ e1d,
                        const int* __restrict__ e2s, const int* __restrict__ e2d,
                        const int* __restrict__ e3s, const int* __restrict__ e3d,
                        const float* __restrict__ w1, const float* __restrict__ w2,
                        const float* __restrict__ w3) {
    int t = blockIdx.x * blockDim.x + threadIdx.x;
    if (t >= NE / 2) return;
    int2 a1 = __ldg((const int2*)e1s + t), b1 = __ldg((const int2*)e1d + t);
    int2 v1 = __ldg((const int2*)w1 + t);
    int2 a2 = __ldg((const int2*)e2s + t), b2 = __ldg((const int2*)e2d + t);
    int2 v2 = __ldg((const int2*)w2 + t);
    int2 a3 = __ldg((const int2*)e3s + t), b3 = __ldg((const int2*)e3d + t);
    int2 v3 = __ldg((const int2*)w3 + t);
    int p0 = atomicAdd(&g_cnt[B_E1D + b1.x], 1) & 127;
    int p1 = atomicAdd(&g_cnt[B_E1D + b1.y], 1) & 127;
    int q0 = atomicAdd(&g_cnt[B_E2D + b2.x], 1) & 127;
    int q1 = atomicAdd(&g_cnt[B_E2D + b2.y], 1) & 127;
    int r0 = atomicAdd(&g_cnt[B_E3D + b3.x], 1) & 127;
    int r1 = atomicAdd(&g_cnt[B_E3D + b3.y], 1) & 127;
    g_giw[WB_E1D + (b1.x << CAPM_SH) + p0] = make_int2(a1.x, v1.x);
    g_giw[WB_E1D + (b1.y << CAPM_SH) + p1] = make_int2(a1.y, v1.y);
    g_giw[WB_E2D + (b2.x << CAPM_SH) + q0] = make_int2(a2.x, v2.x);
    g_giw[WB_E2D + (b2.y << CAPM_SH) + q1] = make_int2(a2.y, v2.y);
    g_giw[WB_E3D + (b3.x << CAPM_SH) + r0] = make_int2(a3.x, v3.x);
    g_giw[WB_E3D + (b3.y << CAPM_SH) + r1] = make_int2(a3.y, v3.y);
}

__global__ void k_fill12(const int* __restrict__ e12s, const int* __restrict__ e12d,
                         const int* __restrict__ e13s, const int* __restrict__ e13d) {
    int t = blockIdx.x * blockDim.x + threadIdx.x;
    if (t >= NE12 / 2) return;
    int2 a4 = __ldg((const int2*)e12s + t), b4 = __ldg((const int2*)e12d + t);
    int2 a5 = __ldg((const int2*)e13s + t), b5 = __ldg((const int2*)e13d + t);
    int p0 = atomicAdd(&g_cnt[B_E12D + b4.x], 1) & 63;
    int p1 = atomicAdd(&g_cnt[B_E12D + b4.y], 1) & 63;
    int q0 = atomicAdd(&g_cnt[B_E12S + a4.x], 1) & 63;
    int q1 = atomicAdd(&g_cnt[B_E12S + a4.y], 1) & 63;
    int r0 = atomicAdd(&g_cnt[B_E13D + b5.x], 1) & 63;
    int r1 = atomicAdd(&g_cnt[B_E13D + b5.y], 1) & 63;
    int s0 = atomicAdd(&g_cnt[B_E13S + a5.x], 1) & 63;
    int s1 = atomicAdd(&g_cnt[B_E13S + a5.y], 1) & 63;
    g_gi[UB_E12D + (b4.x << CAP0_SH) + p0] = a4.x;
    g_gi[UB_E12D + (b4.y << CAP0_SH) + p1] = a4.y;
    g_gi[UB_E12S + (a4.x << CAP0_SH) + q0] = b4.x;
    g_gi[UB_E12S + (a4.y << CAP0_SH) + q1] = b4.y;
    g_gi[UB_E13D + (b5.x << CAP0_SH) + r0] = a5.x;
    g_gi[UB_E13D + (b5.y << CAP0_SH) + r1] = a5.y;
    g_gi[UB_E13S + (a5.x << CAP0_SH) + s0] = b5.x;
    g_gi[UB_E13S + (a5.y << CAP0_SH) + s1] = b5.y;
}

__global__ void k_fillS(const int* __restrict__ e1s, const int* __restrict__ e1d,
                        const int* __restrict__ e2s, const int* __restrict__ e2d,
                        const int* __restrict__ e3s, const int* __restrict__ e3d,
                        const float* __restrict__ w1) {
    int t = blockIdx.x * blockDim.x + threadIdx.x;
    if (t >= NE / 2) return;
    int2 a1 = __ldg((const int2*)e1s + t), b1 = __ldg((const int2*)e1d + t);
    int2 v1 = __ldg((const int2*)w1 + t);
    int2 a2 = __ldg((const int2*)e2s + t), b2 = __ldg((const int2*)e2d + t);
    int2 a3 = __ldg((const int2*)e3s + t), b3 = __ldg((const int2*)e3d + t);
    int p0 = atomicAdd(&g_cnt[B_E1S + a1.x], 1) & 63;
    int p1 = atomicAdd(&g_cnt[B_E1S + a1.y], 1) & 63;
    int q0 = atomicAdd(&g_cnt[B_E2S + a2.x], 1) & 63;
    int q1 = atomicAdd(&g_cnt[B_E2S + a2.y], 1) & 63;
    int r0 = atomicAdd(&g_cnt[B_E3S + a3.x], 1) & 63;
    int r1 = atomicAdd(&g_cnt[B_E3S + a3.y], 1) & 63;
    g_giw[WB_E1S + (a1.x << CAP0_SH) + p0] = make_int2(b1.x, v1.x);
    g_giw[WB_E1S + (a1.y << CAP0_SH) + p1] = make_int2(b1.y, v1.y);
    g_gi[UB_E2S + (a2.x << CAP0_SH) + q0] = b2.x;
    g_gi[UB_E2S + (a2.y << CAP0_SH) + q1] = b2.y;
    g_gi[UB_E3S + (a3.x << CAP0_SH) + r0] = b3.x;
    g_gi[UB_E3S + (a3.y << CAP0_SH) + r1] = b3.y;
}

// ---------------- x_node fp32 -> fp16 ----------------
__global__ void k_cvt(const float* __restrict__ x, __half* __restrict__ y) {
    int i = blockIdx.x * blockDim.x + threadIdx.x;
    if (i >= N0 * 32) return;
    float4 v = __ldg((const float4*)x + i);
    ((uint2*)y)[i] = pack4(v);
}

// ---------------- mega gathers ----------------
// MODE: 0 = int idx unweighted; 1 = int2 weighted; 2 = int2 idx, weight ignored
struct GList {
    const __half* feat;
    const int*    cnt;
    const void*   gidx;
    const float*  xm;
    __half*       out;
    int           nrow;
    int           blk0;
    int           capsh;
};
struct GArgs { GList l[4]; int nlists; };

template<int MODE, bool COMBINE>
__global__ void __launch_bounds__(256) k_gather16(GArgs ga) {
    int li = 0;
    #pragma unroll
    for (int i = 1; i < 4; i++)
        if (i < ga.nlists && (int)blockIdx.x >= ga.l[i].blk0) li = i;
    const GList& L = ga.l[li];

    int n = (blockIdx.x - L.blk0) * 8 + (threadIdx.x >> 5);
    int lane = threadIdx.x & 31;
    if (n >= L.nrow) return;

    const uint2* feat = (const uint2*)L.feat;
    const int2*  giw  = (const int2*)L.gidx;
    const int*   gi   = (const int*)L.gidx;
    int deg = __ldg(L.cnt + n);
    int beg = n << L.capsh;
    int end = beg + deg;

    float4 a0 = make_float4(0.f, 0.f, 0.f, 0.f);
    float4 a1 = a0;
    int e = beg;
    for (; e + 8 <= end; e += 8) {
        int g[8]; float w[8];
        #pragma unroll
        for (int i = 0; i < 8; i++) {
            if (MODE == 0)      { g[i] = __ldg(gi + e + i); w[i] = 1.f; }
            else if (MODE == 1) { int2 p = __ldg(giw + e + i); g[i] = p.x; w[i] = __int_as_float(p.y); }
            else                { int2 p = __ldg(giw + e + i); g[i] = p.x; w[i] = 1.f; }
        }
        uint2 v0 = __ldg(feat + ((unsigned)g[0] << 5) + lane);
        uint2 v1 = __ldg(feat + ((unsigned)g[1] << 5) + lane);
        uint2 v2 = __ldg(feat + ((unsigned)g[2] << 5) + lane);
        uint2 v3 = __ldg(feat + ((unsigned)g[3] << 5) + lane);
        uint2 v4 = __ldg(feat + ((unsigned)g[4] << 5) + lane);
        uint2 v5 = __ldg(feat + ((unsigned)g[5] << 5) + lane);
        uint2 v6 = __ldg(feat + ((unsigned)g[6] << 5) + lane);
        uint2 v7 = __ldg(feat + ((unsigned)g[7] << 5) + lane);
        if (MODE == 1) {
            acc4w(a0, v0, w[0]); acc4w(a1, v1, w[1]);
            acc4w(a0, v2, w[2]); acc4w(a1, v3, w[3]);
            acc4w(a0, v4, w[4]); acc4w(a1, v5, w[5]);
            acc4w(a0, v6, w[6]); acc4w(a1, v7, w[7]);
        } else {
            acc4(a0, v0); acc4(a1, v1); acc4(a0, v2); acc4(a1, v3);
            acc4(a0, v4); acc4(a1, v5); acc4(a0, v6); acc4(a1, v7);
        }
    }
    for (; e < end; e++) {
        int gg; float ww = 1.f;
        if (MODE == 0)      gg = __ldg(gi + e);
        else if (MODE == 1) { int2 p = __ldg(giw + e); gg = p.x; ww = __int_as_float(p.y); }
        else                { int2 p = __ldg(giw + e); gg = p.x; }
        uint2 v = __ldg(feat + ((unsigned)gg << 5) + lane);
        if (MODE == 1) acc4w(a0, v, ww);
        else           acc4(a0, v);
    }
    float4 acc;
    acc.x = a0.x + a1.x; acc.y = a0.y + a1.y;
    acc.z = a0.z + a1.z; acc.w = a0.w + a1.w;
    float r = 1.0f / (float)(deg < 1 ? 1 : deg);
    acc.x *= r; acc.y *= r; acc.z *= r; acc.w *= r;
    if (COMBINE) {
        float4 x = __ldg((const float4*)L.xm + n * 32 + lane);
        acc.x = (acc.x + x.x) * 0.5f;
        acc.y = (acc.y + x.y) * 0.5f;
        acc.z = (acc.z + x.z) * 0.5f;
        acc.w = (acc.w + x.w) * 0.5f;
    }
    ((uint2*)L.out)[n * 32 + lane] = pack4(acc);
}

// ---------------- fused hop4: one E1S walk (int2), 2 weighted fp16 sources ----------------
__global__ void __launch_bounds__(256) k_hop4(const __half* __restrict__ fD,
                                              const __half* __restrict__ fE,
                                              const int* __restrict__ cnt,
                                              const int2* __restrict__ giw,
                                              __half* __restrict__ sD,
                                              __half* __restrict__ sE) {
    int n = blockIdx.x * 8 + (threadIdx.x >> 5);
    int lane = threadIdx.x & 31;
    if (n >= N0) return;
    int deg = __ldg(cnt + n);
    int beg = n << CAP0_SH;
    int end = beg + deg;
    const uint2* D = (const uint2*)fD;
    const uint2* E = (const uint2*)fE;
    float4 aD = make_float4(0.f,0.f,0.f,0.f), aE = aD;
    int e = beg;
    for (; e + 4 <= end; e += 4) {
        int2 p0 = __ldg(giw + e + 0), p1 = __ldg(giw + e + 1);
        int2 p2 = __ldg(giw + e + 2), p3 = __ldg(giw + e + 3);
        float w0 = __int_as_float(p0.y), w1 = __int_as_float(p1.y);
        float w2 = __int_as_float(p2.y), w3 = __int_as_float(p3.y);
        unsigned o0 = ((unsigned)p0.x << 5) + lane;
        unsigned o1 = ((unsigned)p1.x << 5) + lane;
        unsigned o2 = ((unsigned)p2.x << 5) + lane;
        unsigned o3 = ((unsigned)p3.x << 5) + lane;
        uint2 vD0 = __ldg(D + o0), vD1 = __ldg(D + o1), vD2 = __ldg(D + o2), vD3 = __ldg(D + o3);
        uint2 vE0 = __ldg(E + o0), vE1 = __ldg(E + o1), vE2 = __ldg(E + o2), vE3 = __ldg(E + o3);
        acc4w(aD, vD0, w0); acc4w(aD, vD1, w1); acc4w(aD, vD2, w2); acc4w(aD, vD3, w3);
        acc4w(aE, vE0, w0); acc4w(aE, vE1, w1); acc4w(aE, vE2, w2); acc4w(aE, vE3, w3);
    }
    for (; e < end; e++) {
        int2 p = __ldg(giw + e);
        float w = __int_as_float(p.y);
        unsigned o = ((unsigned)p.x << 5) + lane;
        acc4w(aD, __ldg(D + o), w);
        acc4w(aE, __ldg(E + o), w);
    }
    float r = 1.0f / (float)(deg < 1 ? 1 : deg);
    aD.x *= r; aD.y *= r; aD.z *= r; aD.w *= r;
    aE.x *= r; aE.y *= r; aE.z *= r; aE.w *= r;
    unsigned oi = n * 32 + lane;
    ((uint2*)sD)[oi] = pack4(aD);
    ((uint2*)sE)[oi] = pack4(aE);
}

// ---------------- tf32 tensor-core GEMM (single term) + bias + relu ----------------
#define GM   128
#define GP   132
#define GEMM_BLK ((N0 + GM - 1) / GM)
#define GEMM_SM_BYTES (2 * GM * GP * 4)

struct GemmSeg { const __half* sin; const float* W; const float* b; float* obase; };
struct GemmArgs { GemmSeg s[3]; };

__device__ __forceinline__ uint32_t f2tf32(float x) {
    uint32_t r;
    asm("cvt.rna.tf32.f32 %0, %1;" : "=r"(r) : "f"(x));
    return r;
}
__device__ __forceinline__ void mma_tf32(float* c, const uint32_t* a,
                                         uint32_t b0, uint32_t b1) {
    asm("mma.sync.aligned.m16n8k8.row.col.f32.tf32.tf32.f32 "
        "{%0,%1,%2,%3}, {%4,%5,%6,%7}, {%8,%9}, {%0,%1,%2,%3};"
        : "+f"(c[0]), "+f"(c[1]), "+f"(c[2]), "+f"(c[3])
        : "r"(a[0]), "r"(a[1]), "r"(a[2]), "r"(a[3]), "r"(b0), "r"(b1));
}

__global__ void __launch_bounds__(256) k_gemm_tf32(GemmArgs gargs) {
    extern __shared__ float sh[];
    float* Whi = sh;
    float* xs  = sh + GM * GP;
    int tid = threadIdx.x;
    int seg = blockIdx.x / GEMM_BLK;
    int blk = blockIdx.x % GEMM_BLK;
    const GemmSeg S = gargs.s[seg];

    for (int idx = tid; idx < DD * DD / 4; idx += 256) {
        int j = idx >> 5, k4 = (idx & 31) * 4;
        float4 w = __ldg((const float4*)S.W + idx);
        float4 hi;
        hi.x = __uint_as_float(f2tf32(w.x));
        hi.y = __uint_as_float(f2tf32(w.y));
        hi.z = __uint_as_float(f2tf32(w.z));
        hi.w = __uint_as_float(f2tf32(w.w));
        *(float4*)(Whi + j * GP + k4) = hi;
    }
    int row0 = blk * GM;
    for (int idx = tid; idx < GM * 32; idx += 256) {
        int r = idx >> 5, c = idx & 31;
        int row = row0 + r;
        float4 v = make_float4(0.f, 0.f, 0.f, 0.f);
        if (row < N0) {
            uint2 h = __ldg((const uint2*)S.sin + (long long)row * 32 + c);
            float2 p = __half22float2(*(__half2*)&h.x);
            float2 q = __half22float2(*(__half2*)&h.y);
            v = make_float4(p.x, p.y, q.x, q.y);
        }
        *(float4*)(xs + r * GP + c * 4) = v;
    }
    __syncthreads();

    int warp = tid >> 5, lane = tid & 31;
    int rw = warp * 16 + (lane >> 2);
    int kk = lane & 3;
    float acc[16][4];
    #pragma unroll
    for (int t = 0; t < 16; t++) {
        acc[t][0] = 0.f; acc[t][1] = 0.f; acc[t][2] = 0.f; acc[t][3] = 0.f;
    }

    const float* bhp = Whi + (lane >> 2) * GP + kk;

    #pragma unroll 1
    for (int ks = 0; ks < 16; ks++) {
        int k0 = ks * 8;
        uint32_t a[4];
        a[0] = __float_as_uint(xs[rw * GP + k0 + kk]);
        a[1] = __float_as_uint(xs[(rw + 8) * GP + k0 + kk]);
        a[2] = __float_as_uint(xs[rw * GP + k0 + kk + 4]);
        a[3] = __float_as_uint(xs[(rw + 8) * GP + k0 + kk + 4]);
        #pragma unroll
        for (int t = 0; t < 16; t++) {
            int off = t * 8 * GP + k0;
            uint32_t bh0 = __float_as_uint(bhp[off]);
            uint32_t bh1 = __float_as_uint(bhp[off + 4]);
            mma_tf32(acc[t], a, bh0, bh1);
        }
    }

    int jb = 2 * (lane & 3);
    int rg = row0 + warp * 16 + (lane >> 2);
    #pragma unroll
    for (int t = 0; t < 16; t++) {
        int j = t * 8 + jb;
        float2 bb = __ldg((const float2*)(S.b + j));
        if (rg < N0) {
            float2 o;
            o.x = fmaxf(acc[t][0] + bb.x, 0.f);
            o.y = fmaxf(acc[t][1] + bb.y, 0.f);
            *(float2*)(S.obase + (long long)rg * (5 * DD) + j) = o;
        }
        if (rg + 8 < N0) {
            float2 o;
            o.x = fmaxf(acc[t][2] + bb.x, 0.f);
            o.y = fmaxf(acc[t][3] + bb.y, 0.f);
            *(float2*)(S.obase + (long long)(rg + 8) * (5 * DD) + j) = o;
        }
    }
}

// ---------------- attention combine ----------------
__global__ void k_att(const float* __restrict__ attv, float* __restrict__ out) {
    int gt = blockIdx.x * blockDim.x + threadIdx.x;
    int n = gt >> 5;
    int lane = gt & 31;
    if (n >= N0) return;
    const float4* base = (const float4*)(g_allm + (long long)n * (5 * DD));
    float4 a[5];
    float sc[5];
    #pragma unroll
    for (int p = 0; p < 5; p++) {
        a[p] = base[p * 32 + lane];
        float4 av = __ldg((const float4*)attv + p * 32 + lane);
        float d = a[p].x * av.x + a[p].y * av.y + a[p].z * av.z + a[p].w * av.w;
        #pragma unroll
        for (int o = 16; o; o >>= 1) d += __shfl_xor_sync(0xFFFFFFFFu, d, o);
        sc[p] = d;
    }
    float m = sc[0];
    #pragma unroll
    for (int p = 1; p < 5; p++) m = fmaxf(m, sc[p]);
    float ssum = 0.f;
    #pragma unroll
    for (int p = 0; p < 5; p++) { sc[p] = __expf(sc[p] - m); ssum += sc[p]; }
    float inv = 1.0f / ssum;
    float4 o = make_float4(0.f, 0.f, 0.f, 0.f);
    #pragma unroll
    for (int p = 0; p < 5; p++) {
        float wgt = sc[p] * inv;
        o.x += wgt * a[p].x; o.y += wgt * a[p].y;
        o.z += wgt * a[p].z; o.w += wgt * a[p].w;
    }
    ((float4*)out)[(long long)n * 32 + lane] = o;
}

// ---------------- host orchestration ----------------
static inline GList mkl(const __half* feat, const int* cnt, const void* gidx,
                        const float* xm, __half* out, int nrow, int blk0, int capsh) {
    GList L; L.feat = feat; L.cnt = cnt; L.gidx = gidx;
    L.xm = xm; L.out = out; L.nrow = nrow; L.blk0 = blk0; L.capsh = capsh; return L;
}

extern "C" void kernel_launch(void* const* d_in, const int* in_sizes, int n_in,
                              void* d_out, int out_size) {
    const float* x_node = (const float*)d_in[0];
    const float* x1   = (const float*)d_in[1];
    const float* x2   = (const float*)d_in[2];
    const float* x3   = (const float*)d_in[3];
    const float* w1   = (const float*)d_in[4];
    const float* w2   = (const float*)d_in[5];
    const float* w3   = (const float*)d_in[6];
    const float* W1   = (const float*)d_in[7];
    const float* b1   = (const float*)d_in[8];
    const float* W2   = (const float*)d_in[9];
    const float* b2   = (const float*)d_in[10];
    const float* W3   = (const float*)d_in[11];
    const float* b3   = (const float*)d_in[12];
    const float* W121 = (const float*)d_in[13];
    const float* b121 = (const float*)d_in[14];
    const float* W131 = (const float*)d_in[15];
    const float* b131 = (const float*)d_in[16];
    const float* attv = (const float*)d_in[17];
    const int* e1s  = (const int*)d_in[18];
    const int* e1d  = (const int*)d_in[19];
    const int* e2s  = (const int*)d_in[20];
    const int* e2d  = (const int*)d_in[21];
    const int* e3s  = (const int*)d_in[22];
    const int* e3d  = (const int*)d_in[23];
    const int* e12s = (const int*)d_in[24];
    const int* e12d = (const int*)d_in[25];
    const int* e13s = (const int*)d_in[26];
    const int* e13d = (const int*)d_in[27];
    float* out = (float*)d_out;

    __half *xn16, *net1, *midB, *midC, *midD, *n3bD, *midE, *n3bE;
    __half *sumA, *sumB, *sumC, *sumD, *sumE;
    float *allm;
    int *cnt, *gi;
    int2 *giw;
    cudaGetSymbolAddress((void**)&xn16, g_xn16);
    cudaGetSymbolAddress((void**)&net1, g_net1);
    cudaGetSymbolAddress((void**)&midB, g_midB);
    cudaGetSymbolAddress((void**)&midC, g_midC);
    cudaGetSymbolAddress((void**)&midD, g_midD);
    cudaGetSymbolAddress((void**)&n3bD, g_n3bD);
    cudaGetSymbolAddress((void**)&midE, g_midE);
    cudaGetSymbolAddress((void**)&n3bE, g_n3bE);
    cudaGetSymbolAddress((void**)&sumA, g_sumA);
    cudaGetSymbolAddress((void**)&sumB, g_sumB);
    cudaGetSymbolAddress((void**)&sumC, g_sumC);
    cudaGetSymbolAddress((void**)&sumD, g_sumD);
    cudaGetSymbolAddress((void**)&sumE, g_sumE);
    cudaGetSymbolAddress((void**)&allm, g_allm);
    cudaGetSymbolAddress((void**)&cnt,  g_cnt);
    cudaGetSymbolAddress((void**)&gi,   g_gi);
    cudaGetSymbolAddress((void**)&giw,  g_giw);

    cudaFuncSetAttribute(k_gemm_tf32, cudaFuncAttributeMaxDynamicSharedMemorySize,
                         GEMM_SM_BYTES);

    static cudaStream_t s1 = nullptr;
    static cudaEvent_t evZ, evW1, ev12, evS, evS1;
    if (!s1) {
        cudaStreamCreateWithFlags(&s1, cudaStreamNonBlocking);
        cudaEventCreateWithFlags(&evZ,  cudaEventDisableTiming);
        cudaEventCreateWithFlags(&evW1, cudaEventDisableTiming);
        cudaEventCreateWithFlags(&ev12, cudaEventDisableTiming);
        cudaEventCreateWithFlags(&evS,  cudaEventDisableTiming);
        cudaEventCreateWithFlags(&evS1, cudaEventDisableTiming);
    }

    const int T     = 256;
    const int EB2   = (NE / 2 + T - 1) / T;
    const int EB122 = (NE12 / 2 + T - 1) / T;
    const int BM    = (NM + 7) / 8;
    const int BN    = (N0 + 7) / 8;

    // ====== s0: zero counters, cvt, build A ======
    cudaMemsetAsync(cnt, 0, TOTC * sizeof(int), 0);
    cudaEventRecord(evZ, 0);
    k_cvt<<<(N0 * 32 + T - 1) / T, T>>>(x_node, xn16);
    k_fillA<<<EB2, T>>>(e1s, e1d, e2s, e2d, e3s, e3d, w1, w2, w3);

    // ====== s1: build NE12 lists first, then S lists ======
    cudaStreamWaitEvent(s1, evZ, 0);
    k_fill12<<<EB122, T, 0, s1>>>(e12s, e12d, e13s, e13d);
    cudaEventRecord(ev12, s1);
    k_fillS<<<EB2, T, 0, s1>>>(e1s, e1d, e2s, e2d, e3s, e3d, w1);
    cudaEventRecord(evS, s1);

    // ====== s0: wave 1 ======
    {
        GArgs ga; ga.nlists = 3;
        ga.l[0] = mkl(xn16, cnt + B_E1D, giw + WB_E1D, x1, net1, NM, 0, CAPM_SH);
        ga.l[1] = mkl(xn16, cnt + B_E2D, giw + WB_E2D, x2, midB, NM, BM, CAPM_SH);
        ga.l[2] = mkl(xn16, cnt + B_E3D, giw + WB_E3D, x3, midC, NM, 2 * BM, CAPM_SH);
        k_gather16<1, true><<<3 * BM, T>>>(ga);
    }
    cudaEventRecord(evW1, 0);

    // ====== s1: sumA/sumB/sumC gathers + GEMM {A,B,C} ======
    cudaStreamWaitEvent(s1, evW1, 0);
    {
        GArgs ga; ga.nlists = 2;
        ga.l[0] = mkl(midB, cnt + B_E2S, gi + UB_E2S, nullptr, sumB, N0, 0, CAP0_SH);
        ga.l[1] = mkl(midC, cnt + B_E3S, gi + UB_E3S, nullptr, sumC, N0, BN, CAP0_SH);
        k_gather16<0, false><<<2 * BN, T, 0, s1>>>(ga);
    }
    {   // sumA: int2 list (weights ignored), net1 over E1S
        GArgs ga; ga.nlists = 1;
        ga.l[0] = mkl(net1, cnt + B_E1S, giw + WB_E1S, nullptr, sumA, N0, 0, CAP0_SH);
        k_gather16<2, false><<<BN, T, 0, s1>>>(ga);
    }
    {
        GemmArgs gg;
        gg.s[0] = {sumA, W1, b1, allm + 0 * DD};
        gg.s[1] = {sumB, W2, b2, allm + 1 * DD};
        gg.s[2] = {sumC, W3, b3, allm + 2 * DD};
        k_gemm_tf32<<<3 * GEMM_BLK, T, GEMM_SM_BYTES, s1>>>(gg);
    }
    cudaEventRecord(evS1, s1);

    // ====== s0: long paths ======
    cudaStreamWaitEvent(0, ev12, 0);
    {
        GArgs ga; ga.nlists = 2;
        ga.l[0] = mkl(net1, cnt + B_E12D, gi + UB_E12D, x2, midD, NM, 0, CAP0_SH);
        ga.l[1] = mkl(net1, cnt + B_E13D, gi + UB_E13D, x3, midE, NM, BM, CAP0_SH);
        k_gather16<0, true><<<2 * BM, T>>>(ga);
    }
    {
        GArgs ga; ga.nlists = 2;
        ga.l[0] = mkl(midD, cnt + B_E12S, gi + UB_E12S, x1, n3bD, NM, 0, CAP0_SH);
        ga.l[1] = mkl(midE, cnt + B_E13S, gi + UB_E13S, x1, n3bE, NM, BM, CAP0_SH);
        k_gather16<0, true><<<2 * BM, T>>>(ga);
    }
    cudaStreamWaitEvent(0, evS, 0);
    k_hop4<<<BN, T>>>(n3bD, n3bE, cnt + B_E1S, giw + WB_E1S, sumD, sumE);
    {
        GemmArgs gg;
        gg.s[0] = {sumD, W121, b121, allm + 3 * DD};
        gg.s[1] = {sumE, W131, b131, allm + 4 * DD};
        gg.s[2] = {sumD, W121, b121, allm + 3 * DD};  // unused
        k_gemm_tf32<<<2 * GEMM_BLK, T, GEMM_SM_BYTES>>>(gg);
    }

    // ====== join + attention ======
    cudaStreamWaitEvent(0, evS1, 0);
    k_att<<<(N0 + 7) / 8, T>>>(attv, out);
}

// round 17
// speedup vs baseline: 1.4001x; 1.4001x over previous
#include <cuda_runtime.h>
#include <cuda_fp16.h>
#include <cstdint>

#define N0   50000
#define NM   25000
#define DD   128
#define NE   800000
#define NE12 400000

// ---------------- per-list counters ----------------
#define B_E1D  0
#define B_E2D  (B_E1D + NM)
#define B_E3D  (B_E2D + NM)
#define B_E1S  (B_E3D + NM)
#define B_E2S  (B_E1S + N0)
#define B_E3S  (B_E2S + N0)
#define B_E12D (B_E3S + N0)
#define B_E12S (B_E12D + NM)
#define B_E13D (B_E12S + NM)
#define B_E13S (B_E13D + NM)
#define TOTC   (B_E13S + NM)

// ---------------- padded bucket storage ----------------
#define CAPM_SH 7
#define CAP0_SH 6
#define WB_E1D 0
#define WB_E2D (WB_E1D + (NM << CAPM_SH))
#define WB_E3D (WB_E2D + (NM << CAPM_SH))
#define WB_E1S (WB_E3D + (NM << CAPM_SH))
#define TOTW   (WB_E1S + (N0 << CAP0_SH))
#define UB_E2S  0
#define UB_E3S  (UB_E2S + (N0 << CAP0_SH))
#define UB_E12D (UB_E3S + (N0 << CAP0_SH))
#define UB_E12S (UB_E12D + (NM << CAP0_SH))
#define UB_E13D (UB_E12S + (NM << CAP0_SH))
#define UB_E13S (UB_E13D + (NM << CAP0_SH))
#define TOTU    (UB_E13S + (NM << CAP0_SH))

// ---------------- static device scratch ----------------
__device__ int    g_cnt[TOTC];
__device__ int2   g_giw[TOTW];
__device__ int    g_gi[TOTU];

__device__ __half g_xn16[(long long)N0 * DD];
__device__ __half g_net1[NM * DD];
__device__ __half g_midB[NM * DD];
__device__ __half g_midC[NM * DD];
__device__ __half g_midD[NM * DD];
__device__ __half g_n3bD[NM * DD];
__device__ __half g_midE[NM * DD];
__device__ __half g_n3bE[NM * DD];
__device__ __half g_sumA[(long long)N0 * DD];
__device__ __half g_sumB[(long long)N0 * DD];
__device__ __half g_sumC[(long long)N0 * DD];
__device__ __half g_sumD[(long long)N0 * DD];
__device__ __half g_sumE[(long long)N0 * DD];
__device__ float  g_allm[(long long)N0 * 5 * DD];

// ---------------- fp16 helpers ----------------
__device__ __forceinline__ void acc4w(float4& a, uint2 v, float w) {
    float2 p = __half22float2(*(__half2*)&v.x);
    float2 q = __half22float2(*(__half2*)&v.y);
    a.x += p.x * w; a.y += p.y * w; a.z += q.x * w; a.w += q.y * w;
}
__device__ __forceinline__ void acc4(float4& a, uint2 v) {
    float2 p = __half22float2(*(__half2*)&v.x);
    float2 q = __half22float2(*(__half2*)&v.y);
    a.x += p.x; a.y += p.y; a.z += q.x; a.w += q.y;
}
__device__ __forceinline__ uint2 pack4(float4 a) {
    __half2 h0 = __floats2half2_rn(a.x, a.y);
    __half2 h1 = __floats2half2_rn(a.z, a.w);
    uint2 r; r.x = *(unsigned*)&h0; r.y = *(unsigned*)&h1; return r;
}

// ---------------- one-pass bucketed build (2 edges/thread) ----------------
__global__ void k_fillA(const int* __restrict__ e1s, const int* __restrict__ e1d,
                        const int* __restrict__ e2s, const int* __restrict__ e2d,
                        const int* __restrict__ e3s, const int* __restrict__ e3d,
                        const float* __restrict__ w1, const float* __restrict__ w2,
                        const float* __restrict__ w3) {
    int t = blockIdx.x * blockDim.x + threadIdx.x;
    if (t >= NE / 2) return;
    int2 a1 = __ldg((const int2*)e1s + t), b1 = __ldg((const int2*)e1d + t);
    int2 v1 = __ldg((const int2*)w1 + t);
    int2 a2 = __ldg((const int2*)e2s + t), b2 = __ldg((const int2*)e2d + t);
    int2 v2 = __ldg((const int2*)w2 + t);
    int2 a3 = __ldg((const int2*)e3s + t), b3 = __ldg((const int2*)e3d + t);
    int2 v3 = __ldg((const int2*)w3 + t);
    int p0 = atomicAdd(&g_cnt[B_E1D + b1.x], 1) & 127;
    int p1 = atomicAdd(&g_cnt[B_E1D + b1.y], 1) & 127;
    int q0 = atomicAdd(&g_cnt[B_E2D + b2.x], 1) & 127;
    int q1 = atomicAdd(&g_cnt[B_E2D + b2.y], 1) & 127;
    int r0 = atomicAdd(&g_cnt[B_E3D + b3.x], 1) & 127;
    int r1 = atomicAdd(&g_cnt[B_E3D + b3.y], 1) & 127;
    g_giw[WB_E1D + (b1.x << CAPM_SH) + p0] = make_int2(a1.x, v1.x);
    g_giw[WB_E1D + (b1.y << CAPM_SH) + p1] = make_int2(a1.y, v1.y);
    g_giw[WB_E2D + (b2.x << CAPM_SH) + q0] = make_int2(a2.x, v2.x);
    g_giw[WB_E2D + (b2.y << CAPM_SH) + q1] = make_int2(a2.y, v2.y);
    g_giw[WB_E3D + (b3.x << CAPM_SH) + r0] = make_int2(a3.x, v3.x);
    g_giw[WB_E3D + (b3.y << CAPM_SH) + r1] = make_int2(a3.y, v3.y);
}

__global__ void k_fill12(const int* __restrict__ e12s, const int* __restrict__ e12d,
                         const int* __restrict__ e13s, const int* __restrict__ e13d) {
    int t = blockIdx.x * blockDim.x + threadIdx.x;
    if (t >= NE12 / 2) return;
    int2 a4 = __ldg((const int2*)e12s + t), b4 = __ldg((const int2*)e12d + t);
    int2 a5 = __ldg((const int2*)e13s + t), b5 = __ldg((const int2*)e13d + t);
    int p0 = atomicAdd(&g_cnt[B_E12D + b4.x], 1) & 63;
    int p1 = atomicAdd(&g_cnt[B_E12D + b4.y], 1) & 63;
    int q0 = atomicAdd(&g_cnt[B_E12S + a4.x], 1) & 63;
    int q1 = atomicAdd(&g_cnt[B_E12S + a4.y], 1) & 63;
    int r0 = atomicAdd(&g_cnt[B_E13D + b5.x], 1) & 63;
    int r1 = atomicAdd(&g_cnt[B_E13D + b5.y], 1) & 63;
    int s0 = atomicAdd(&g_cnt[B_E13S + a5.x], 1) & 63;
    int s1 = atomicAdd(&g_cnt[B_E13S + a5.y], 1) & 63;
    g_gi[UB_E12D + (b4.x << CAP0_SH) + p0] = a4.x;
    g_gi[UB_E12D + (b4.y << CAP0_SH) + p1] = a4.y;
    g_gi[UB_E12S + (a4.x << CAP0_SH) + q0] = b4.x;
    g_gi[UB_E12S + (a4.y << CAP0_SH) + q1] = b4.y;
    g_gi[UB_E13D + (b5.x << CAP0_SH) + r0] = a5.x;
    g_gi[UB_E13D + (b5.y << CAP0_SH) + r1] = a5.y;
    g_gi[UB_E13S + (a5.x << CAP0_SH) + s0] = b5.x;
    g_gi[UB_E13S + (a5.y << CAP0_SH) + s1] = b5.y;
}

__global__ void k_fillS(const int* __restrict__ e1s, const int* __restrict__ e1d,
                        const int* __restrict__ e2s, const int* __restrict__ e2d,
                        const int* __restrict__ e3s, const int* __restrict__ e3d,
                        const float* __restrict__ w1) {
    int t = blockIdx.x * blockDim.x + threadIdx.x;
    if (t >= NE / 2) return;
    int2 a1 = __ldg((const int2*)e1s + t), b1 = __ldg((const int2*)e1d + t);
    int2 v1 = __ldg((const int2*)w1 + t);
    int2 a2 = __ldg((const int2*)e2s + t), b2 = __ldg((const int2*)e2d + t);
    int2 a3 = __ldg((const int2*)e3s + t), b3 = __ldg((const int2*)e3d + t);
    int p0 = atomicAdd(&g_cnt[B_E1S + a1.x], 1) & 63;
    int p1 = atomicAdd(&g_cnt[B_E1S + a1.y], 1) & 63;
    int q0 = atomicAdd(&g_cnt[B_E2S + a2.x], 1) & 63;
    int q1 = atomicAdd(&g_cnt[B_E2S + a2.y], 1) & 63;
    int r0 = atomicAdd(&g_cnt[B_E3S + a3.x], 1) & 63;
    int r1 = atomicAdd(&g_cnt[B_E3S + a3.y], 1) & 63;
    g_giw[WB_E1S + (a1.x << CAP0_SH) + p0] = make_int2(b1.x, v1.x);
    g_giw[WB_E1S + (a1.y << CAP0_SH) + p1] = make_int2(b1.y, v1.y);
    g_gi[UB_E2S + (a2.x << CAP0_SH) + q0] = b2.x;
    g_gi[UB_E2S + (a2.y << CAP0_SH) + q1] = b2.y;
    g_gi[UB_E3S + (a3.x << CAP0_SH) + r0] = b3.x;
    g_gi[UB_E3S + (a3.y << CAP0_SH) + r1] = b3.y;
}

// ---------------- x_node fp32 -> fp16 ----------------
__global__ void k_cvt(const float* __restrict__ x, __half* __restrict__ y) {
    int i = blockIdx.x * blockDim.x + threadIdx.x;
    if (i >= N0 * 32) return;
    float4 v = __ldg((const float4*)x + i);
    ((uint2*)y)[i] = pack4(v);
}

// ---------------- mega gathers ----------------
// MODE: 0 = int idx unweighted; 1 = int2 weighted; 2 = int2 idx, weight ignored
struct GList {
    const __half* feat;
    const int*    cnt;
    const void*   gidx;
    const float*  xm;
    __half*       out;
    int           nrow;
    int           blk0;
    int           capsh;
};
struct GArgs { GList l[4]; int nlists; };

template<int MODE, bool COMBINE>
__global__ void __launch_bounds__(256) k_gather16(GArgs ga) {
    int li = 0;
    #pragma unroll
    for (int i = 1; i < 4; i++)
        if (i < ga.nlists && (int)blockIdx.x >= ga.l[i].blk0) li = i;
    const GList& L = ga.l[li];

    int n = (blockIdx.x - L.blk0) * 8 + (threadIdx.x >> 5);
    int lane = threadIdx.x & 31;
    if (n >= L.nrow) return;

    const uint2* feat = (const uint2*)L.feat;
    const int2*  giw  = (const int2*)L.gidx;
    const int*   gi   = (const int*)L.gidx;
    int deg = __ldg(L.cnt + n);
    int beg = n << L.capsh;
    int end = beg + deg;

    float4 a0 = make_float4(0.f, 0.f, 0.f, 0.f);
    float4 a1 = a0;
    int e = beg;
    for (; e + 8 <= end; e += 8) {
        int g[8]; float w[8];
        #pragma unroll
        for (int i = 0; i < 8; i++) {
            if (MODE == 0)      { g[i] = __ldg(gi + e + i); w[i] = 1.f; }
            else if (MODE == 1) { int2 p = __ldg(giw + e + i); g[i] = p.x; w[i] = __int_as_float(p.y); }
            else                { int2 p = __ldg(giw + e + i); g[i] = p.x; w[i] = 1.f; }
        }
        uint2 v0 = __ldg(feat + ((unsigned)g[0] << 5) + lane);
        uint2 v1 = __ldg(feat + ((unsigned)g[1] << 5) + lane);
        uint2 v2 = __ldg(feat + ((unsigned)g[2] << 5) + lane);
        uint2 v3 = __ldg(feat + ((unsigned)g[3] << 5) + lane);
        uint2 v4 = __ldg(feat + ((unsigned)g[4] << 5) + lane);
        uint2 v5 = __ldg(feat + ((unsigned)g[5] << 5) + lane);
        uint2 v6 = __ldg(feat + ((unsigned)g[6] << 5) + lane);
        uint2 v7 = __ldg(feat + ((unsigned)g[7] << 5) + lane);
        if (MODE == 1) {
            acc4w(a0, v0, w[0]); acc4w(a1, v1, w[1]);
            acc4w(a0, v2, w[2]); acc4w(a1, v3, w[3]);
            acc4w(a0, v4, w[4]); acc4w(a1, v5, w[5]);
            acc4w(a0, v6, w[6]); acc4w(a1, v7, w[7]);
        } else {
            acc4(a0, v0); acc4(a1, v1); acc4(a0, v2); acc4(a1, v3);
            acc4(a0, v4); acc4(a1, v5); acc4(a0, v6); acc4(a1, v7);
        }
    }
    for (; e < end; e++) {
        int gg; float ww = 1.f;
        if (MODE == 0)      gg = __ldg(gi + e);
        else if (MODE == 1) { int2 p = __ldg(giw + e); gg = p.x; ww = __int_as_float(p.y); }
        else                { int2 p = __ldg(giw + e); gg = p.x; }
        uint2 v = __ldg(feat + ((unsigned)gg << 5) + lane);
        if (MODE == 1) acc4w(a0, v, ww);
        else           acc4(a0, v);
    }
    float4 acc;
    acc.x = a0.x + a1.x; acc.y = a0.y + a1.y;
    acc.z = a0.z + a1.z; acc.w = a0.w + a1.w;
    float r = 1.0f / (float)(deg < 1 ? 1 : deg);
    acc.x *= r; acc.y *= r; acc.z *= r; acc.w *= r;
    if (COMBINE) {
        float4 x = __ldg((const float4*)L.xm + n * 32 + lane);
        acc.x = (acc.x + x.x) * 0.5f;
        acc.y = (acc.y + x.y) * 0.5f;
        acc.z = (acc.z + x.z) * 0.5f;
        acc.w = (acc.w + x.w) * 0.5f;
    }
    ((uint2*)L.out)[n * 32 + lane] = pack4(acc);
}

// ---------------- fused hop4: one E1S walk (int2), 2 weighted fp16 sources ----------------
__global__ void __launch_bounds__(256) k_hop4(const __half* __restrict__ fD,
                                              const __half* __restrict__ fE,
                                              const int* __restrict__ cnt,
                                              const int2* __restrict__ giw,
                                              __half* __restrict__ sD,
                                              __half* __restrict__ sE) {
    int n = blockIdx.x * 8 + (threadIdx.x >> 5);
    int lane = threadIdx.x & 31;
    if (n >= N0) return;
    int deg = __ldg(cnt + n);
    int beg = n << CAP0_SH;
    int end = beg + deg;
    const uint2* D = (const uint2*)fD;
    const uint2* E = (const uint2*)fE;
    float4 aD = make_float4(0.f,0.f,0.f,0.f), aE = aD;
    int e = beg;
    for (; e + 4 <= end; e += 4) {
        int2 p0 = __ldg(giw + e + 0), p1 = __ldg(giw + e + 1);
        int2 p2 = __ldg(giw + e + 2), p3 = __ldg(giw + e + 3);
        float w0 = __int_as_float(p0.y), w1 = __int_as_float(p1.y);
        float w2 = __int_as_float(p2.y), w3 = __int_as_float(p3.y);
        unsigned o0 = ((unsigned)p0.x << 5) + lane;
        unsigned o1 = ((unsigned)p1.x << 5) + lane;
        unsigned o2 = ((unsigned)p2.x << 5) + lane;
        unsigned o3 = ((unsigned)p3.x << 5) + lane;
        uint2 vD0 = __ldg(D + o0), vD1 = __ldg(D + o1), vD2 = __ldg(D + o2), vD3 = __ldg(D + o3);
        uint2 vE0 = __ldg(E + o0), vE1 = __ldg(E + o1), vE2 = __ldg(E + o2), vE3 = __ldg(E + o3);
        acc4w(aD, vD0, w0); acc4w(aD, vD1, w1); acc4w(aD, vD2, w2); acc4w(aD, vD3, w3);
        acc4w(aE, vE0, w0); acc4w(aE, vE1, w1); acc4w(aE, vE2, w2); acc4w(aE, vE3, w3);
    }
    for (; e < end; e++) {
        int2 p = __ldg(giw + e);
        float w = __int_as_float(p.y);
        unsigned o = ((unsigned)p.x << 5) + lane;
        acc4w(aD, __ldg(D + o), w);
        acc4w(aE, __ldg(E + o), w);
    }
    float r = 1.0f / (float)(deg < 1 ? 1 : deg);
    aD.x *= r; aD.y *= r; aD.z *= r; aD.w *= r;
    aE.x *= r; aE.y *= r; aE.z *= r; aE.w *= r;
    unsigned oi = n * 32 + lane;
    ((uint2*)sD)[oi] = pack4(aD);
    ((uint2*)sE)[oi] = pack4(aE);
}

// ---------------- fp16 tensor-core GEMM (m16n8k16, fp32 accum) + bias + relu ----------------
#define GM   128
#define PU   68   // uint pitch per row (136 halves; banks (4g+kk) conflict-free)
#define GEMM_BLK ((N0 + GM - 1) / GM)
#define GEMM_SM_BYTES (2 * GM * PU * 4)

struct GemmSeg { const __half* sin; const float* W; const float* b; float* obase; };
struct GemmArgs { GemmSeg s[3]; };

__device__ __forceinline__ void mma_f16(float* c, uint32_t a0, uint32_t a1,
                                        uint32_t a2, uint32_t a3,
                                        uint32_t b0, uint32_t b1) {
    asm("mma.sync.aligned.m16n8k16.row.col.f32.f16.f16.f32 "
        "{%0,%1,%2,%3}, {%4,%5,%6,%7}, {%8,%9}, {%0,%1,%2,%3};"
        : "+f"(c[0]), "+f"(c[1]), "+f"(c[2]), "+f"(c[3])
        : "r"(a0), "r"(a1), "r"(a2), "r"(a3), "r"(b0), "r"(b1));
}

__global__ void __launch_bounds__(256) k_gemm_f16(GemmArgs gargs) {
    extern __shared__ uint32_t shu[];
    uint32_t* Wh = shu;            // [j][k/2] fp16x2, pitch PU
    uint32_t* xs = shu + GM * PU;  // [r][k/2] fp16x2, pitch PU
    int tid = threadIdx.x;
    int seg = blockIdx.x / GEMM_BLK;
    int blk = blockIdx.x % GEMM_BLK;
    const GemmSeg S = gargs.s[seg];

    // load W (fp32) -> fp16 pairs in smem
    for (int idx = tid; idx < DD * DD / 4; idx += 256) {
        int j = idx >> 5, c4 = (idx & 31) * 2;   // uint index within row
        float4 w = __ldg((const float4*)S.W + idx);
        __half2 h0 = __floats2half2_rn(w.x, w.y);
        __half2 h1 = __floats2half2_rn(w.z, w.w);
        Wh[j * PU + c4 + 0] = *(uint32_t*)&h0;
        Wh[j * PU + c4 + 1] = *(uint32_t*)&h1;
    }
    // load x tile (already fp16): 64 uints per row
    int row0 = blk * GM;
    for (int idx = tid; idx < GM * 64; idx += 256) {
        int r = idx >> 6, c = idx & 63;
        int row = row0 + r;
        uint32_t v = 0u;
        if (row < N0) v = __ldg((const uint32_t*)S.sin + (long long)row * 64 + c);
        xs[r * PU + c] = v;
    }
    __syncthreads();

    int warp = tid >> 5, lane = tid & 31;
    int g = lane >> 2, kk = lane & 3;
    const uint32_t* xr0 = xs + (warp * 16 + g) * PU;
    const uint32_t* xr1 = xr0 + 8 * PU;
    float acc[16][4];
    #pragma unroll
    for (int t = 0; t < 16; t++) {
        acc[t][0] = 0.f; acc[t][1] = 0.f; acc[t][2] = 0.f; acc[t][3] = 0.f;
    }

    #pragma unroll 1
    for (int ks = 0; ks < 8; ks++) {
        int ku = ks * 8;   // uint offset (16 halves per step)
        uint32_t a0 = xr0[ku + kk];
        uint32_t a1 = xr1[ku + kk];
        uint32_t a2 = xr0[ku + 4 + kk];
        uint32_t a3 = xr1[ku + 4 + kk];
        #pragma unroll
        for (int t = 0; t < 16; t++) {
            const uint32_t* wr = Wh + (t * 8 + g) * PU + ku;
            uint32_t b0 = wr[kk];
            uint32_t b1 = wr[4 + kk];
            mma_f16(acc[t], a0, a1, a2, a3, b0, b1);
        }
    }

    int jb = 2 * (lane & 3);
    int rg = row0 + warp * 16 + g;
    #pragma unroll
    for (int t = 0; t < 16; t++) {
        int j = t * 8 + jb;
        float2 bb = __ldg((const float2*)(S.b + j));
        if (rg < N0) {
            float2 o;
            o.x = fmaxf(acc[t][0] + bb.x, 0.f);
            o.y = fmaxf(acc[t][1] + bb.y, 0.f);
            *(float2*)(S.obase + (long long)rg * (5 * DD) + j) = o;
        }
        if (rg + 8 < N0) {
            float2 o;
            o.x = fmaxf(acc[t][2] + bb.x, 0.f);
            o.y = fmaxf(acc[t][3] + bb.y, 0.f);
            *(float2*)(S.obase + (long long)(rg + 8) * (5 * DD) + j) = o;
        }
    }
}

// ---------------- attention combine ----------------
__global__ void k_att(const float* __restrict__ attv, float* __restrict__ out) {
    int gt = blockIdx.x * blockDim.x + threadIdx.x;
    int n = gt >> 5;
    int lane = gt & 31;
    if (n >= N0) return;
    const float4* base = (const float4*)(g_allm + (long long)n * (5 * DD));
    float4 a[5];
    float sc[5];
    #pragma unroll
    for (int p = 0; p < 5; p++) {
        a[p] = base[p * 32 + lane];
        float4 av = __ldg((const float4*)attv + p * 32 + lane);
        float d = a[p].x * av.x + a[p].y * av.y + a[p].z * av.z + a[p].w * av.w;
        #pragma unroll
        for (int o = 16; o; o >>= 1) d += __shfl_xor_sync(0xFFFFFFFFu, d, o);
        sc[p] = d;
    }
    float m = sc[0];
    #pragma unroll
    for (int p = 1; p < 5; p++) m = fmaxf(m, sc[p]);
    float ssum = 0.f;
    #pragma unroll
    for (int p = 0; p < 5; p++) { sc[p] = __expf(sc[p] - m); ssum += sc[p]; }
    float inv = 1.0f / ssum;
    float4 o = make_float4(0.f, 0.f, 0.f, 0.f);
    #pragma unroll
    for (int p = 0; p < 5; p++) {
        float wgt = sc[p] * inv;
        o.x += wgt * a[p].x; o.y += wgt * a[p].y;
        o.z += wgt * a[p].z; o.w += wgt * a[p].w;
    }
    ((float4*)out)[(long long)n * 32 + lane] = o;
}

// ---------------- host orchestration ----------------
static inline GList mkl(const __half* feat, const int* cnt, const void* gidx,
                        const float* xm, __half* out, int nrow, int blk0, int capsh) {
    GList L; L.feat = feat; L.cnt = cnt; L.gidx = gidx;
    L.xm = xm; L.out = out; L.nrow = nrow; L.blk0 = blk0; L.capsh = capsh; return L;
}

extern "C" void kernel_launch(void* const* d_in, const int* in_sizes, int n_in,
                              void* d_out, int out_size) {
    const float* x_node = (const float*)d_in[0];
    const float* x1   = (const float*)d_in[1];
    const float* x2   = (const float*)d_in[2];
    const float* x3   = (const float*)d_in[3];
    const float* w1   = (const float*)d_in[4];
    const float* w2   = (const float*)d_in[5];
    const float* w3   = (const float*)d_in[6];
    const float* W1   = (const float*)d_in[7];
    const float* b1   = (const float*)d_in[8];
    const float* W2   = (const float*)d_in[9];
    const float* b2   = (const float*)d_in[10];
    const float* W3   = (const float*)d_in[11];
    const float* b3   = (const float*)d_in[12];
    const float* W121 = (const float*)d_in[13];
    const float* b121 = (const float*)d_in[14];
    const float* W131 = (const float*)d_in[15];
    const float* b131 = (const float*)d_in[16];
    const float* attv = (const float*)d_in[17];
    const int* e1s  = (const int*)d_in[18];
    const int* e1d  = (const int*)d_in[19];
    const int* e2s  = (const int*)d_in[20];
    const int* e2d  = (const int*)d_in[21];
    const int* e3s  = (const int*)d_in[22];
    const int* e3d  = (const int*)d_in[23];
    const int* e12s = (const int*)d_in[24];
    const int* e12d = (const int*)d_in[25];
    const int* e13s = (const int*)d_in[26];
    const int* e13d = (const int*)d_in[27];
    float* out = (float*)d_out;

    __half *xn16, *net1, *midB, *midC, *midD, *n3bD, *midE, *n3bE;
    __half *sumA, *sumB, *sumC, *sumD, *sumE;
    float *allm;
    int *cnt, *gi;
    int2 *giw;
    cudaGetSymbolAddress((void**)&xn16, g_xn16);
    cudaGetSymbolAddress((void**)&net1, g_net1);
    cudaGetSymbolAddress((void**)&midB, g_midB);
    cudaGetSymbolAddress((void**)&midC, g_midC);
    cudaGetSymbolAddress((void**)&midD, g_midD);
    cudaGetSymbolAddress((void**)&n3bD, g_n3bD);
    cudaGetSymbolAddress((void**)&midE, g_midE);
    cudaGetSymbolAddress((void**)&n3bE, g_n3bE);
    cudaGetSymbolAddress((void**)&sumA, g_sumA);
    cudaGetSymbolAddress((void**)&sumB, g_sumB);
    cudaGetSymbolAddress((void**)&sumC, g_sumC);
    cudaGetSymbolAddress((void**)&sumD, g_sumD);
    cudaGetSymbolAddress((void**)&sumE, g_sumE);
    cudaGetSymbolAddress((void**)&allm, g_allm);
    cudaGetSymbolAddress((void**)&cnt,  g_cnt);
    cudaGetSymbolAddress((void**)&gi,   g_gi);
    cudaGetSymbolAddress((void**)&giw,  g_giw);

    cudaFuncSetAttribute(k_gemm_f16, cudaFuncAttributeMaxDynamicSharedMemorySize,
                         GEMM_SM_BYTES);

    static cudaStream_t s1 = nullptr;
    static cudaEvent_t evZ, evW1, ev12, evS, evS1;
    if (!s1) {
        cudaStreamCreateWithFlags(&s1, cudaStreamNonBlocking);
        cudaEventCreateWithFlags(&evZ,  cudaEventDisableTiming);
        cudaEventCreateWithFlags(&evW1, cudaEventDisableTiming);
        cudaEventCreateWithFlags(&ev12, cudaEventDisableTiming);
        cudaEventCreateWithFlags(&evS,  cudaEventDisableTiming);
        cudaEventCreateWithFlags(&evS1, cudaEventDisableTiming);
    }

    const int T     = 256;
    const int EB2   = (NE / 2 + T - 1) / T;
    const int EB122 = (NE12 / 2 + T - 1) / T;
    const int BM    = (NM + 7) / 8;
    const int BN    = (N0 + 7) / 8;

    // ====== s0: zero counters, cvt, build A ======
    cudaMemsetAsync(cnt, 0, TOTC * sizeof(int), 0);
    cudaEventRecord(evZ, 0);
    k_cvt<<<(N0 * 32 + T - 1) / T, T>>>(x_node, xn16);
    k_fillA<<<EB2, T>>>(e1s, e1d, e2s, e2d, e3s, e3d, w1, w2, w3);

    // ====== s1: build NE12 lists first, then S lists ======
    cudaStreamWaitEvent(s1, evZ, 0);
    k_fill12<<<EB122, T, 0, s1>>>(e12s, e12d, e13s, e13d);
    cudaEventRecord(ev12, s1);
    k_fillS<<<EB2, T, 0, s1>>>(e1s, e1d, e2s, e2d, e3s, e3d, w1);
    cudaEventRecord(evS, s1);

    // ====== s0: wave 1 ======
    {
        GArgs ga; ga.nlists = 3;
        ga.l[0] = mkl(xn16, cnt + B_E1D, giw + WB_E1D, x1, net1, NM, 0, CAPM_SH);
        ga.l[1] = mkl(xn16, cnt + B_E2D, giw + WB_E2D, x2, midB, NM, BM, CAPM_SH);
        ga.l[2] = mkl(xn16, cnt + B_E3D, giw + WB_E3D, x3, midC, NM, 2 * BM, CAPM_SH);
        k_gather16<1, true><<<3 * BM, T>>>(ga);
    }
    cudaEventRecord(evW1, 0);

    // ====== s1: sumA/sumB/sumC gathers + GEMM {A,B,C} ======
    cudaStreamWaitEvent(s1, evW1, 0);
    {
        GArgs ga; ga.nlists = 2;
        ga.l[0] = mkl(midB, cnt + B_E2S, gi + UB_E2S, nullptr, sumB, N0, 0, CAP0_SH);
        ga.l[1] = mkl(midC, cnt + B_E3S, gi + UB_E3S, nullptr, sumC, N0, BN, CAP0_SH);
        k_gather16<0, false><<<2 * BN, T, 0, s1>>>(ga);
    }
    {   // sumA: int2 list (weights ignored), net1 over E1S
        GArgs ga; ga.nlists = 1;
        ga.l[0] = mkl(net1, cnt + B_E1S, giw + WB_E1S, nullptr, sumA, N0, 0, CAP0_SH);
        k_gather16<2, false><<<BN, T, 0, s1>>>(ga);
    }
    {
        GemmArgs gg;
        gg.s[0] = {sumA, W1, b1, allm + 0 * DD};
        gg.s[1] = {sumB, W2, b2, allm + 1 * DD};
        gg.s[2] = {sumC, W3, b3, allm + 2 * DD};
        k_gemm_f16<<<3 * GEMM_BLK, T, GEMM_SM_BYTES, s1>>>(gg);
    }
    cudaEventRecord(evS1, s1);

    // ====== s0: long paths ======
    cudaStreamWaitEvent(0, ev12, 0);
    {
        GArgs ga; ga.nlists = 2;
        ga.l[0] = mkl(net1, cnt + B_E12D, gi + UB_E12D, x2, midD, NM, 0, CAP0_SH);
        ga.l[1] = mkl(net1, cnt + B_E13D, gi + UB_E13D, x3, midE, NM, BM, CAP0_SH);
        k_gather16<0, true><<<2 * BM, T>>>(ga);
    }
    {
        GArgs ga; ga.nlists = 2;
        ga.l[0] = mkl(midD, cnt + B_E12S, gi + UB_E12S, x1, n3bD, NM, 0, CAP0_SH);
        ga.l[1] = mkl(midE, cnt + B_E13S, gi + UB_E13S, x1, n3bE, NM, BM, CAP0_SH);
        k_gather16<0, true><<<2 * BM, T>>>(ga);
    }
    cudaStreamWaitEvent(0, evS, 0);
    k_hop4<<<BN, T>>>(n3bD, n3bE, cnt + B_E1S, giw + WB_E1S, sumD, sumE);
    {
        GemmArgs gg;
        gg.s[0] = {sumD, W121, b121, allm + 3 * DD};
        gg.s[1] = {sumE, W131, b131, allm + 4 * DD};
        gg.s[2] = {sumD, W121, b121, allm + 3 * DD};  // unused
        k_gemm_f16<<<2 * GEMM_BLK, T, GEMM_SM_BYTES>>>(gg);
    }

    // ====== join + attention ======
    cudaStreamWaitEvent(0, evS1, 0);
    k_att<<<(N0 + 7) / 8, T>>>(attv, out);
}